// round 3
// baseline (speedup 1.0000x reference)
#include <cuda_runtime.h>
#include <cuda_bf16.h>
#include <math.h>

// Problem constants
#define B_   2
#define S_   2048
#define D_   2048
#define H_   16
#define KV_  4
#define HD_  128
#define NROWS (B_*S_)        // 4096
#define QPK_ (H_/KV_)        // 4

// ---------------- scratch (device globals; no allocation allowed) ----------
__device__ float g_q[(size_t)NROWS * D_];        // [b,s,h,hd]  33.5 MB
__device__ float g_k[(size_t)NROWS * KV_ * HD_]; // [b,s,kv,hd]  8.4 MB
__device__ float g_v[(size_t)NROWS * KV_ * HD_];
__device__ float g_attn[(size_t)NROWS * D_];     // attention out, [b,s,h,hd]

// ---------------- generic SGEMM: C[M,N] = A[M,K] @ B[K,N] (+ bias) ---------
// BM=BN=128, BK=16, 256 threads, 8x8 register tile per thread.
__global__ __launch_bounds__(256) void sgemm_kernel(
    const float* __restrict__ A, const float* __restrict__ Bm,
    const float* __restrict__ bias, float* __restrict__ C,
    int M, int N, int K)
{
    __shared__ float As[16][128];   // transposed: As[k][m]
    __shared__ float Bs[16][128];   // Bs[k][n]

    const int tid = threadIdx.x;
    const int tx  = tid & 15;
    const int ty  = tid >> 4;
    const int m0  = blockIdx.y * 128;
    const int n0  = blockIdx.x * 128;

    float acc[8][8];
#pragma unroll
    for (int i = 0; i < 8; i++)
#pragma unroll
        for (int j = 0; j < 8; j++) acc[i][j] = 0.f;

    const float* Ab = A + (size_t)m0 * K;
    const float* Bb = Bm + n0;

    for (int k0 = 0; k0 < K; k0 += 16) {
        // A tile: 128 rows x 16 cols = 512 float4
#pragma unroll
        for (int s = 0; s < 2; s++) {
            int f  = tid + 256 * s;
            int r  = f >> 2;              // 0..127
            int c4 = (f & 3) << 2;        // 0,4,8,12
            float4 v = *(const float4*)(Ab + (size_t)r * K + k0 + c4);
            As[c4 + 0][r] = v.x;
            As[c4 + 1][r] = v.y;
            As[c4 + 2][r] = v.z;
            As[c4 + 3][r] = v.w;
        }
        // B tile: 16 rows x 128 cols = 512 float4
#pragma unroll
        for (int s = 0; s < 2; s++) {
            int f  = tid + 256 * s;
            int r  = f >> 5;              // 0..15
            int c4 = (f & 31) << 2;       // 0..124
            *(float4*)(&Bs[r][c4]) = *(const float4*)(Bb + (size_t)(k0 + r) * N + c4);
        }
        __syncthreads();

#pragma unroll
        for (int k = 0; k < 16; k++) {
            float a[8], b[8];
            *(float4*)&a[0] = *(const float4*)&As[k][ty * 8];
            *(float4*)&a[4] = *(const float4*)&As[k][ty * 8 + 4];
            *(float4*)&b[0] = *(const float4*)&Bs[k][tx * 8];
            *(float4*)&b[4] = *(const float4*)&Bs[k][tx * 8 + 4];
#pragma unroll
            for (int i = 0; i < 8; i++)
#pragma unroll
                for (int j = 0; j < 8; j++)
                    acc[i][j] += a[i] * b[j];
        }
        __syncthreads();
    }

    // epilogue: optional bias, vectorized store
#pragma unroll
    for (int i = 0; i < 8; i++) {
        int m = m0 + ty * 8 + i;
        float* Crow = C + (size_t)m * N + n0 + tx * 8;
#pragma unroll
        for (int j = 0; j < 8; j += 4) {
            float4 v;
            v.x = acc[i][j + 0];
            v.y = acc[i][j + 1];
            v.z = acc[i][j + 2];
            v.w = acc[i][j + 3];
            if (bias) {
                const float* bp = bias + n0 + tx * 8 + j;
                v.x += bp[0]; v.y += bp[1]; v.z += bp[2]; v.w += bp[3];
            }
            *(float4*)(Crow + j) = v;
        }
    }
}

// ---------------- RoPE (interleaved pairs, per reference) -------------------
// q layout [b,s,h,hd]: pair p -> elements 2p, 2p+1; j = p % 64; s = p/(64*H) % S
// k layout [b,s,kv,hd]: j = p % 64; s = p/(64*KV) % S
__global__ void rope_kernel(float* __restrict__ q, float* __restrict__ k,
                            const float* __restrict__ fcos,
                            const float* __restrict__ fsin)
{
    const int NQP = B_ * S_ * H_  * (HD_ / 2);   // 4194304
    const int NKP = B_ * S_ * KV_ * (HD_ / 2);   // 1048576
    int idx = blockIdx.x * blockDim.x + threadIdx.x;
    if (idx < NQP) {
        int j = idx & 63;
        int s = (idx >> 10) & (S_ - 1);          // / (64*16)
        float c  = fcos[s * 64 + j];
        float sn = fsin[s * 64 + j];
        float2 v = *(float2*)(q + 2 * (size_t)idx);
        float2 o;
        o.x = v.x * c - v.y * sn;
        o.y = v.x * sn + v.y * c;
        *(float2*)(q + 2 * (size_t)idx) = o;
    } else if (idx < NQP + NKP) {
        int p = idx - NQP;
        int j = p & 63;
        int s = (p >> 8) & (S_ - 1);             // / (64*4)
        float c  = fcos[s * 64 + j];
        float sn = fsin[s * 64 + j];
        float2 v = *(float2*)(k + 2 * (size_t)p);
        float2 o;
        o.x = v.x * c - v.y * sn;
        o.y = v.x * sn + v.y * c;
        *(float2*)(k + 2 * (size_t)p) = o;
    }
}

// ---------------- Flash attention (causal, GQA) -----------------------------
// Block: (qb, h, b). 64 query rows, kv tiles of 64. 256 threads = 16x16.
// Thread (ty,tx): score rows 4ty+i (i<4), score cols tx+16j (j<4),
//                 O cols 8tx..8tx+7.
#define PADR 132   // 128 + 4 padding (row stride for Q/KV tiles)
#define PADP 68    // 64 + 4 padding (row stride for P tile)
#define ATT_SMEM_BYTES ((64*PADR*2 + 64*PADP) * 4)   // 84992

__global__ __launch_bounds__(256) void flash_attn_kernel(
    const float* __restrict__ Q, const float* __restrict__ Kg,
    const float* __restrict__ Vg, float* __restrict__ O)
{
    extern __shared__ float sm[];
    float* Qs  = sm;                  // 64 x PADR
    float* KVs = sm + 64 * PADR;      // 64 x PADR (K, then reused for V)
    float* Ps  = KVs + 64 * PADR;     // 64 x PADP

    const int tid = threadIdx.x;
    const int tx  = tid & 15;
    const int ty  = tid >> 4;
    const int qb  = blockIdx.x;       // 0..31
    const int h   = blockIdx.y;       // 0..15
    const int b   = blockIdx.z;       // 0..1
    const int kvh = h >> 2;
    const float scale = 0.08838834764831845f;   // 1/sqrt(128)

    // load Q tile (64 x 128), rows at stride H*HD = 2048 floats
    const float* qbase = Q + (((size_t)(b * S_ + qb * 64)) * H_ + h) * HD_;
#pragma unroll
    for (int s = 0; s < 8; s++) {
        int f = tid + 256 * s;        // 0..2047 float4s
        int r = f >> 5;
        int c = (f & 31) << 2;
        *(float4*)(Qs + r * PADR + c) =
            *(const float4*)(qbase + (size_t)r * (H_ * HD_) + c);
    }

    float m_i[4], l_i[4], o[4][8];
#pragma unroll
    for (int i = 0; i < 4; i++) {
        m_i[i] = -1e30f;
        l_i[i] = 0.f;
#pragma unroll
        for (int c = 0; c < 8; c++) o[i][c] = 0.f;
    }

    for (int kb = 0; kb <= qb; kb++) {
        __syncthreads();   // prior PV reads of KVs done (and Q store on iter 0)
        // load K tile, rows at stride KV*HD = 512 floats
        const float* kbase = Kg + (((size_t)(b * S_ + kb * 64)) * KV_ + kvh) * HD_;
#pragma unroll
        for (int s = 0; s < 8; s++) {
            int f = tid + 256 * s;
            int r = f >> 5;
            int c = (f & 31) << 2;
            *(float4*)(KVs + r * PADR + c) =
                *(const float4*)(kbase + (size_t)r * (KV_ * HD_) + c);
        }
        __syncthreads();

        // scores: sc[i][j] = Q[4ty+i] . K[tx+16j]
        float sc[4][4];
#pragma unroll
        for (int i = 0; i < 4; i++)
#pragma unroll
            for (int j = 0; j < 4; j++) sc[i][j] = 0.f;

#pragma unroll 4
        for (int d = 0; d < 128; d += 4) {
            float4 qv[4], kv[4];
#pragma unroll
            for (int i = 0; i < 4; i++)
                qv[i] = *(const float4*)(Qs + (4 * ty + i) * PADR + d);
#pragma unroll
            for (int j = 0; j < 4; j++)
                kv[j] = *(const float4*)(KVs + (tx + 16 * j) * PADR + d);
#pragma unroll
            for (int i = 0; i < 4; i++)
#pragma unroll
                for (int j = 0; j < 4; j++) {
                    sc[i][j] += qv[i].x * kv[j].x;
                    sc[i][j] += qv[i].y * kv[j].y;
                    sc[i][j] += qv[i].z * kv[j].z;
                    sc[i][j] += qv[i].w * kv[j].w;
                }
        }

        // scale + causal mask
#pragma unroll
        for (int i = 0; i < 4; i++) {
            int qrow = qb * 64 + 4 * ty + i;
#pragma unroll
            for (int j = 0; j < 4; j++) {
                int kcol = kb * 64 + tx + 16 * j;
                sc[i][j] = (kcol <= qrow) ? sc[i][j] * scale : -1e30f;
            }
        }

        // online softmax (row reduce across the 16 tx lanes of each half-warp)
#pragma unroll
        for (int i = 0; i < 4; i++) {
            float mx = fmaxf(fmaxf(sc[i][0], sc[i][1]), fmaxf(sc[i][2], sc[i][3]));
#pragma unroll
            for (int off = 8; off > 0; off >>= 1)
                mx = fmaxf(mx, __shfl_xor_sync(0xffffffffu, mx, off));
            float mn    = fmaxf(m_i[i], mx);
            float alpha = __expf(m_i[i] - mn);
            m_i[i] = mn;
            float rs = 0.f;
#pragma unroll
            for (int j = 0; j < 4; j++) {
                float p = __expf(sc[i][j] - mn);
                sc[i][j] = p;
                rs += p;
            }
#pragma unroll
            for (int off = 8; off > 0; off >>= 1)
                rs += __shfl_xor_sync(0xffffffffu, rs, off);
            l_i[i] = l_i[i] * alpha + rs;
#pragma unroll
            for (int c = 0; c < 8; c++) o[i][c] *= alpha;
#pragma unroll
            for (int j = 0; j < 4; j++)
                Ps[(4 * ty + i) * PADP + tx + 16 * j] = sc[i][j];
        }
        __syncthreads();   // Ps written; KVs reads for scores complete

        // load V tile over KVs
        const float* vbase = Vg + (((size_t)(b * S_ + kb * 64)) * KV_ + kvh) * HD_;
#pragma unroll
        for (int s = 0; s < 8; s++) {
            int f = tid + 256 * s;
            int r = f >> 5;
            int c = (f & 31) << 2;
            *(float4*)(KVs + r * PADR + c) =
                *(const float4*)(vbase + (size_t)r * (KV_ * HD_) + c);
        }
        __syncthreads();

        // O += P @ V   (O cols 8tx..8tx+7)
#pragma unroll 4
        for (int kk = 0; kk < 64; kk++) {
            float p0 = Ps[(4 * ty + 0) * PADP + kk];
            float p1 = Ps[(4 * ty + 1) * PADP + kk];
            float p2 = Ps[(4 * ty + 2) * PADP + kk];
            float p3 = Ps[(4 * ty + 3) * PADP + kk];
            float4 v0 = *(const float4*)(KVs + kk * PADR + tx * 8);
            float4 v1 = *(const float4*)(KVs + kk * PADR + tx * 8 + 4);
            o[0][0] += p0 * v0.x; o[0][1] += p0 * v0.y; o[0][2] += p0 * v0.z; o[0][3] += p0 * v0.w;
            o[0][4] += p0 * v1.x; o[0][5] += p0 * v1.y; o[0][6] += p0 * v1.z; o[0][7] += p0 * v1.w;
            o[1][0] += p1 * v0.x; o[1][1] += p1 * v0.y; o[1][2] += p1 * v0.z; o[1][3] += p1 * v0.w;
            o[1][4] += p1 * v1.x; o[1][5] += p1 * v1.y; o[1][6] += p1 * v1.z; o[1][7] += p1 * v1.w;
            o[2][0] += p2 * v0.x; o[2][1] += p2 * v0.y; o[2][2] += p2 * v0.z; o[2][3] += p2 * v0.w;
            o[2][4] += p2 * v1.x; o[2][5] += p2 * v1.y; o[2][6] += p2 * v1.z; o[2][7] += p2 * v1.w;
            o[3][0] += p3 * v0.x; o[3][1] += p3 * v0.y; o[3][2] += p3 * v0.z; o[3][3] += p3 * v0.w;
            o[3][4] += p3 * v1.x; o[3][5] += p3 * v1.y; o[3][6] += p3 * v1.z; o[3][7] += p3 * v1.w;
        }
    }

    // normalize + write O[b, qrow, h, :]
#pragma unroll
    for (int i = 0; i < 4; i++) {
        float inv = 1.0f / l_i[i];
        int qrow = qb * 64 + 4 * ty + i;
        float* obase = O + (((size_t)(b * S_ + qrow)) * H_ + h) * HD_ + tx * 8;
        float4 w0, w1;
        w0.x = o[i][0] * inv; w0.y = o[i][1] * inv; w0.z = o[i][2] * inv; w0.w = o[i][3] * inv;
        w1.x = o[i][4] * inv; w1.y = o[i][5] * inv; w1.z = o[i][6] * inv; w1.w = o[i][7] * inv;
        *(float4*)(obase)     = w0;
        *(float4*)(obase + 4) = w1;
    }
}

// ---------------- launch ----------------------------------------------------
extern "C" void kernel_launch(void* const* d_in, const int* in_sizes, int n_in,
                              void* d_out, int out_size)
{
    const float* x    = (const float*)d_in[0];
    // d_in[1] = mask (all zeros; unused by the reference math)
    const float* fcos = (const float*)d_in[2];
    const float* fsin = (const float*)d_in[3];
    const float* Wq   = (const float*)d_in[4];
    const float* bq   = (const float*)d_in[5];
    const float* Wk   = (const float*)d_in[6];
    const float* bk   = (const float*)d_in[7];
    const float* Wv   = (const float*)d_in[8];
    const float* bv   = (const float*)d_in[9];
    const float* Wo   = (const float*)d_in[10];
    float* out = (float*)d_out;

    float *q, *k, *v, *attn;
    cudaGetSymbolAddress((void**)&q,    g_q);
    cudaGetSymbolAddress((void**)&k,    g_k);
    cudaGetSymbolAddress((void**)&v,    g_v);
    cudaGetSymbolAddress((void**)&attn, g_attn);

    // QKV projections (+bias)
    sgemm_kernel<<<dim3(D_ / 128, NROWS / 128), 256>>>(x, Wq, bq, q, NROWS, D_, D_);
    sgemm_kernel<<<dim3((KV_ * HD_) / 128, NROWS / 128), 256>>>(x, Wk, bk, k, NROWS, KV_ * HD_, D_);
    sgemm_kernel<<<dim3((KV_ * HD_) / 128, NROWS / 128), 256>>>(x, Wv, bv, v, NROWS, KV_ * HD_, D_);

    // RoPE on Q and K (in place)
    {
        const int NQP = B_ * S_ * H_  * (HD_ / 2);
        const int NKP = B_ * S_ * KV_ * (HD_ / 2);
        int total = NQP + NKP;
        rope_kernel<<<(total + 255) / 256, 256>>>(q, k, fcos, fsin);
    }

    // causal flash attention
    cudaFuncSetAttribute(flash_attn_kernel,
                         cudaFuncAttributeMaxDynamicSharedMemorySize,
                         ATT_SMEM_BYTES);
    flash_attn_kernel<<<dim3(S_ / 64, H_, B_), 256, ATT_SMEM_BYTES>>>(q, k, v, attn);

    // output projection -> d_out
    sgemm_kernel<<<dim3(D_ / 128, NROWS / 128), 256>>>(attn, Wo, nullptr, out, NROWS, D_, D_);
}

// round 4
// speedup vs baseline: 1.7358x; 1.7358x over previous
#include <cuda_runtime.h>
#include <cuda_bf16.h>
#include <math.h>

// Problem constants
#define B_   2
#define S_   2048
#define D_   2048
#define H_   16
#define KV_  4
#define HD_  128
#define NROWS (B_*S_)        // 4096
#define QPK_ (H_/KV_)        // 4

// ---------------- scratch (device globals; no allocation allowed) ----------
__device__ float g_q[(size_t)NROWS * D_];        // [b,s,h,hd]
__device__ float g_k[(size_t)NROWS * KV_ * HD_]; // [b,s,kv,hd]
__device__ float g_v[(size_t)NROWS * KV_ * HD_];
__device__ float g_attn[(size_t)NROWS * D_];     // attention out, [b,s,h,hd]

// ---------------- tf32 helpers ----------------------------------------------
__device__ __forceinline__ unsigned f2tf(float f) {
    unsigned r;
    asm("cvt.rna.tf32.f32 %0, %1;" : "=r"(r) : "f"(f));
    return r;
}

__device__ __forceinline__ void mma_tf32(float c[4],
                                         unsigned a0, unsigned a1,
                                         unsigned a2, unsigned a3,
                                         unsigned b0, unsigned b1) {
    asm volatile(
        "mma.sync.aligned.m16n8k8.row.col.f32.tf32.tf32.f32 "
        "{%0,%1,%2,%3}, {%4,%5,%6,%7}, {%8,%9}, {%0,%1,%2,%3};\n"
        : "+f"(c[0]), "+f"(c[1]), "+f"(c[2]), "+f"(c[3])
        : "r"(a0), "r"(a1), "r"(a2), "r"(a3), "r"(b0), "r"(b1));
}

// ---------------- TF32 tensor-core GEMM: C[M,N] = A[M,K] @ B[K,N] (+bias) ---
// 128x128 tile, BK=32, 256 threads = 8 warps (2x4), warp tile 64x32.
// As[m][k] pad 4 (stride 36): a-frag banks 4*(lane/4)+(lane%4) -> conflict-free
// Bs[k][n] pad 8 (stride 136): b-frag banks 8*(lane%4)+(lane/4) -> conflict-free
__global__ __launch_bounds__(256, 2) void tf32_gemm_kernel(
    const float* __restrict__ A, const float* __restrict__ Bm,
    const float* __restrict__ bias, float* __restrict__ C,
    int M, int N, int K)
{
    __shared__ unsigned As[128][36];
    __shared__ unsigned Bs[32][136];

    const int tid  = threadIdx.x;
    const int warp = tid >> 5;
    const int lane = tid & 31;
    const int wm   = warp >> 2;        // 0..1
    const int wn   = warp & 3;         // 0..3
    const int grp  = lane >> 2;        // 0..7
    const int qid  = lane & 3;         // 0..3
    const int m0   = blockIdx.y * 128;
    const int n0   = blockIdx.x * 128;

    float acc[4][4][4];
#pragma unroll
    for (int mi = 0; mi < 4; mi++)
#pragma unroll
        for (int ni = 0; ni < 4; ni++)
#pragma unroll
            for (int r = 0; r < 4; r++) acc[mi][ni][r] = 0.f;

    const float* Aptr = A + (size_t)m0 * K;
    const float* Bptr = Bm + n0;

    float4 stA[4], stB[4];

    // ---- tile load/store helpers (inlined) ----
    // A: idx = tid+256s: r = idx>>3 (0..127), c4 = (idx&7)*4  (coalesced 128B rows)
    // B: idx = tid+256s: r = idx>>5 (0..31),  c4 = (idx&31)*4 (coalesced 512B rows)
#define LOAD_TILES(k0)                                                         \
    {                                                                          \
        _Pragma("unroll")                                                      \
        for (int s = 0; s < 4; s++) {                                          \
            int idx = tid + 256 * s;                                           \
            int r = idx >> 3, c4 = (idx & 7) << 2;                             \
            stA[s] = *(const float4*)(Aptr + (size_t)r * K + (k0) + c4);       \
        }                                                                      \
        _Pragma("unroll")                                                      \
        for (int s = 0; s < 4; s++) {                                          \
            int idx = tid + 256 * s;                                           \
            int r = idx >> 5, c4 = (idx & 31) << 2;                            \
            stB[s] = *(const float4*)(Bptr + (size_t)((k0) + r) * N + c4);     \
        }                                                                      \
    }

#define STORE_TILES()                                                          \
    {                                                                          \
        _Pragma("unroll")                                                      \
        for (int s = 0; s < 4; s++) {                                          \
            int idx = tid + 256 * s;                                           \
            int r = idx >> 3, c4 = (idx & 7) << 2;                             \
            uint4 u;                                                           \
            u.x = f2tf(stA[s].x); u.y = f2tf(stA[s].y);                        \
            u.z = f2tf(stA[s].z); u.w = f2tf(stA[s].w);                        \
            *(uint4*)&As[r][c4] = u;                                           \
        }                                                                      \
        _Pragma("unroll")                                                      \
        for (int s = 0; s < 4; s++) {                                          \
            int idx = tid + 256 * s;                                           \
            int r = idx >> 5, c4 = (idx & 31) << 2;                            \
            uint4 u;                                                           \
            u.x = f2tf(stB[s].x); u.y = f2tf(stB[s].y);                        \
            u.z = f2tf(stB[s].z); u.w = f2tf(stB[s].w);                        \
            *(uint4*)&Bs[r][c4] = u;                                           \
        }                                                                      \
    }

    const int nk = K >> 5;   // K / 32
    LOAD_TILES(0);
    STORE_TILES();
    __syncthreads();

    for (int kt = 0; kt < nk; kt++) {
        if (kt + 1 < nk) LOAD_TILES((kt + 1) << 5);

        // compute on current smem tiles
#pragma unroll
        for (int ks = 0; ks < 4; ks++) {
            const int k = ks * 8;
            unsigned a[4][4], b[4][2];
#pragma unroll
            for (int mi = 0; mi < 4; mi++) {
                int m = wm * 64 + mi * 16;
                a[mi][0] = As[m + grp][k + qid];
                a[mi][1] = As[m + grp + 8][k + qid];
                a[mi][2] = As[m + grp][k + qid + 4];
                a[mi][3] = As[m + grp + 8][k + qid + 4];
            }
#pragma unroll
            for (int ni = 0; ni < 4; ni++) {
                int n = wn * 32 + ni * 8;
                b[ni][0] = Bs[k + qid][n + grp];
                b[ni][1] = Bs[k + qid + 4][n + grp];
            }
#pragma unroll
            for (int mi = 0; mi < 4; mi++)
#pragma unroll
                for (int ni = 0; ni < 4; ni++)
                    mma_tf32(acc[mi][ni],
                             a[mi][0], a[mi][1], a[mi][2], a[mi][3],
                             b[ni][0], b[ni][1]);
        }
        __syncthreads();
        if (kt + 1 < nk) {
            STORE_TILES();
            __syncthreads();
        }
    }

    // epilogue: c0,c1 = (row, 2q),(row, 2q+1); c2,c3 = row+8
#pragma unroll
    for (int mi = 0; mi < 4; mi++) {
#pragma unroll
        for (int ni = 0; ni < 4; ni++) {
            int row = m0 + wm * 64 + mi * 16 + grp;
            int col = n0 + wn * 32 + ni * 8 + 2 * qid;
            float bx = 0.f, by = 0.f;
            if (bias) { bx = bias[col]; by = bias[col + 1]; }
            float2 v0, v1;
            v0.x = acc[mi][ni][0] + bx; v0.y = acc[mi][ni][1] + by;
            v1.x = acc[mi][ni][2] + bx; v1.y = acc[mi][ni][3] + by;
            *(float2*)(C + (size_t)row * N + col)       = v0;
            *(float2*)(C + (size_t)(row + 8) * N + col) = v1;
        }
    }
#undef LOAD_TILES
#undef STORE_TILES
}

// ---------------- RoPE (interleaved pairs, per reference) -------------------
__global__ void rope_kernel(float* __restrict__ q, float* __restrict__ k,
                            const float* __restrict__ fcos,
                            const float* __restrict__ fsin)
{
    const int NQP = B_ * S_ * H_  * (HD_ / 2);
    const int NKP = B_ * S_ * KV_ * (HD_ / 2);
    int idx = blockIdx.x * blockDim.x + threadIdx.x;
    if (idx < NQP) {
        int j = idx & 63;
        int s = (idx >> 10) & (S_ - 1);
        float c  = fcos[s * 64 + j];
        float sn = fsin[s * 64 + j];
        float2 v = *(float2*)(q + 2 * (size_t)idx);
        float2 o;
        o.x = v.x * c - v.y * sn;
        o.y = v.x * sn + v.y * c;
        *(float2*)(q + 2 * (size_t)idx) = o;
    } else if (idx < NQP + NKP) {
        int p = idx - NQP;
        int j = p & 63;
        int s = (p >> 8) & (S_ - 1);
        float c  = fcos[s * 64 + j];
        float sn = fsin[s * 64 + j];
        float2 v = *(float2*)(k + 2 * (size_t)p);
        float2 o;
        o.x = v.x * c - v.y * sn;
        o.y = v.x * sn + v.y * c;
        *(float2*)(k + 2 * (size_t)p) = o;
    }
}

// ---------------- Flash attention (causal, GQA) — fp32, unchanged -----------
#define PADR 132
#define PADP 68
#define ATT_SMEM_BYTES ((64*PADR*2 + 64*PADP) * 4)   // 84992

__global__ __launch_bounds__(256) void flash_attn_kernel(
    const float* __restrict__ Q, const float* __restrict__ Kg,
    const float* __restrict__ Vg, float* __restrict__ O)
{
    extern __shared__ float sm[];
    float* Qs  = sm;
    float* KVs = sm + 64 * PADR;
    float* Ps  = KVs + 64 * PADR;

    const int tid = threadIdx.x;
    const int tx  = tid & 15;
    const int ty  = tid >> 4;
    const int qb  = blockIdx.x;
    const int h   = blockIdx.y;
    const int b   = blockIdx.z;
    const int kvh = h >> 2;
    const float scale = 0.08838834764831845f;

    const float* qbase = Q + (((size_t)(b * S_ + qb * 64)) * H_ + h) * HD_;
#pragma unroll
    for (int s = 0; s < 8; s++) {
        int f = tid + 256 * s;
        int r = f >> 5;
        int c = (f & 31) << 2;
        *(float4*)(Qs + r * PADR + c) =
            *(const float4*)(qbase + (size_t)r * (H_ * HD_) + c);
    }

    float m_i[4], l_i[4], o[4][8];
#pragma unroll
    for (int i = 0; i < 4; i++) {
        m_i[i] = -1e30f;
        l_i[i] = 0.f;
#pragma unroll
        for (int c = 0; c < 8; c++) o[i][c] = 0.f;
    }

    for (int kb = 0; kb <= qb; kb++) {
        __syncthreads();
        const float* kbase = Kg + (((size_t)(b * S_ + kb * 64)) * KV_ + kvh) * HD_;
#pragma unroll
        for (int s = 0; s < 8; s++) {
            int f = tid + 256 * s;
            int r = f >> 5;
            int c = (f & 31) << 2;
            *(float4*)(KVs + r * PADR + c) =
                *(const float4*)(kbase + (size_t)r * (KV_ * HD_) + c);
        }
        __syncthreads();

        float sc[4][4];
#pragma unroll
        for (int i = 0; i < 4; i++)
#pragma unroll
            for (int j = 0; j < 4; j++) sc[i][j] = 0.f;

#pragma unroll 4
        for (int d = 0; d < 128; d += 4) {
            float4 qv[4], kv[4];
#pragma unroll
            for (int i = 0; i < 4; i++)
                qv[i] = *(const float4*)(Qs + (4 * ty + i) * PADR + d);
#pragma unroll
            for (int j = 0; j < 4; j++)
                kv[j] = *(const float4*)(KVs + (tx + 16 * j) * PADR + d);
#pragma unroll
            for (int i = 0; i < 4; i++)
#pragma unroll
                for (int j = 0; j < 4; j++) {
                    sc[i][j] += qv[i].x * kv[j].x;
                    sc[i][j] += qv[i].y * kv[j].y;
                    sc[i][j] += qv[i].z * kv[j].z;
                    sc[i][j] += qv[i].w * kv[j].w;
                }
        }

#pragma unroll
        for (int i = 0; i < 4; i++) {
            int qrow = qb * 64 + 4 * ty + i;
#pragma unroll
            for (int j = 0; j < 4; j++) {
                int kcol = kb * 64 + tx + 16 * j;
                sc[i][j] = (kcol <= qrow) ? sc[i][j] * scale : -1e30f;
            }
        }

#pragma unroll
        for (int i = 0; i < 4; i++) {
            float mx = fmaxf(fmaxf(sc[i][0], sc[i][1]), fmaxf(sc[i][2], sc[i][3]));
#pragma unroll
            for (int off = 8; off > 0; off >>= 1)
                mx = fmaxf(mx, __shfl_xor_sync(0xffffffffu, mx, off));
            float mn    = fmaxf(m_i[i], mx);
            float alpha = __expf(m_i[i] - mn);
            m_i[i] = mn;
            float rs = 0.f;
#pragma unroll
            for (int j = 0; j < 4; j++) {
                float p = __expf(sc[i][j] - mn);
                sc[i][j] = p;
                rs += p;
            }
#pragma unroll
            for (int off = 8; off > 0; off >>= 1)
                rs += __shfl_xor_sync(0xffffffffu, rs, off);
            l_i[i] = l_i[i] * alpha + rs;
#pragma unroll
            for (int c = 0; c < 8; c++) o[i][c] *= alpha;
#pragma unroll
            for (int j = 0; j < 4; j++)
                Ps[(4 * ty + i) * PADP + tx + 16 * j] = sc[i][j];
        }
        __syncthreads();

        const float* vbase = Vg + (((size_t)(b * S_ + kb * 64)) * KV_ + kvh) * HD_;
#pragma unroll
        for (int s = 0; s < 8; s++) {
            int f = tid + 256 * s;
            int r = f >> 5;
            int c = (f & 31) << 2;
            *(float4*)(KVs + r * PADR + c) =
                *(const float4*)(vbase + (size_t)r * (KV_ * HD_) + c);
        }
        __syncthreads();

#pragma unroll 4
        for (int kk = 0; kk < 64; kk++) {
            float p0 = Ps[(4 * ty + 0) * PADP + kk];
            float p1 = Ps[(4 * ty + 1) * PADP + kk];
            float p2 = Ps[(4 * ty + 2) * PADP + kk];
            float p3 = Ps[(4 * ty + 3) * PADP + kk];
            float4 v0 = *(const float4*)(KVs + kk * PADR + tx * 8);
            float4 v1 = *(const float4*)(KVs + kk * PADR + tx * 8 + 4);
            o[0][0] += p0 * v0.x; o[0][1] += p0 * v0.y; o[0][2] += p0 * v0.z; o[0][3] += p0 * v0.w;
            o[0][4] += p0 * v1.x; o[0][5] += p0 * v1.y; o[0][6] += p0 * v1.z; o[0][7] += p0 * v1.w;
            o[1][0] += p1 * v0.x; o[1][1] += p1 * v0.y; o[1][2] += p1 * v0.z; o[1][3] += p1 * v0.w;
            o[1][4] += p1 * v1.x; o[1][5] += p1 * v1.y; o[1][6] += p1 * v1.z; o[1][7] += p1 * v1.w;
            o[2][0] += p2 * v0.x; o[2][1] += p2 * v0.y; o[2][2] += p2 * v0.z; o[2][3] += p2 * v0.w;
            o[2][4] += p2 * v1.x; o[2][5] += p2 * v1.y; o[2][6] += p2 * v1.z; o[2][7] += p2 * v1.w;
            o[3][0] += p3 * v0.x; o[3][1] += p3 * v0.y; o[3][2] += p3 * v0.z; o[3][3] += p3 * v0.w;
            o[3][4] += p3 * v1.x; o[3][5] += p3 * v1.y; o[3][6] += p3 * v1.z; o[3][7] += p3 * v1.w;
        }
    }

#pragma unroll
    for (int i = 0; i < 4; i++) {
        float inv = 1.0f / l_i[i];
        int qrow = qb * 64 + 4 * ty + i;
        float* obase = O + (((size_t)(b * S_ + qrow)) * H_ + h) * HD_ + tx * 8;
        float4 w0, w1;
        w0.x = o[i][0] * inv; w0.y = o[i][1] * inv; w0.z = o[i][2] * inv; w0.w = o[i][3] * inv;
        w1.x = o[i][4] * inv; w1.y = o[i][5] * inv; w1.z = o[i][6] * inv; w1.w = o[i][7] * inv;
        *(float4*)(obase)     = w0;
        *(float4*)(obase + 4) = w1;
    }
}

// ---------------- launch ----------------------------------------------------
extern "C" void kernel_launch(void* const* d_in, const int* in_sizes, int n_in,
                              void* d_out, int out_size)
{
    const float* x    = (const float*)d_in[0];
    const float* fcos = (const float*)d_in[2];
    const float* fsin = (const float*)d_in[3];
    const float* Wq   = (const float*)d_in[4];
    const float* bq   = (const float*)d_in[5];
    const float* Wk   = (const float*)d_in[6];
    const float* bk   = (const float*)d_in[7];
    const float* Wv   = (const float*)d_in[8];
    const float* bv   = (const float*)d_in[9];
    const float* Wo   = (const float*)d_in[10];
    float* out = (float*)d_out;

    float *q, *k, *v, *attn;
    cudaGetSymbolAddress((void**)&q,    g_q);
    cudaGetSymbolAddress((void**)&k,    g_k);
    cudaGetSymbolAddress((void**)&v,    g_v);
    cudaGetSymbolAddress((void**)&attn, g_attn);

    // QKV projections (+bias) on tensor cores (tf32)
    tf32_gemm_kernel<<<dim3(D_ / 128, NROWS / 128), 256>>>(x, Wq, bq, q, NROWS, D_, D_);
    tf32_gemm_kernel<<<dim3((KV_ * HD_) / 128, NROWS / 128), 256>>>(x, Wk, bk, k, NROWS, KV_ * HD_, D_);
    tf32_gemm_kernel<<<dim3((KV_ * HD_) / 128, NROWS / 128), 256>>>(x, Wv, bv, v, NROWS, KV_ * HD_, D_);

    // RoPE on Q and K (in place)
    {
        const int NQP = B_ * S_ * H_  * (HD_ / 2);
        const int NKP = B_ * S_ * KV_ * (HD_ / 2);
        int total = NQP + NKP;
        rope_kernel<<<(total + 255) / 256, 256>>>(q, k, fcos, fsin);
    }

    // causal flash attention (fp32)
    cudaFuncSetAttribute(flash_attn_kernel,
                         cudaFuncAttributeMaxDynamicSharedMemorySize,
                         ATT_SMEM_BYTES);
    flash_attn_kernel<<<dim3(S_ / 64, H_, B_), 256, ATT_SMEM_BYTES>>>(q, k, v, attn);

    // output projection -> d_out (tf32 tensor cores)
    tf32_gemm_kernel<<<dim3(D_ / 128, NROWS / 128), 256>>>(attn, Wo, nullptr, out, NROWS, D_, D_);
}

// round 5
// speedup vs baseline: 3.1895x; 1.8376x over previous
#include <cuda_runtime.h>
#include <cuda_bf16.h>
#include <math.h>

// Problem constants
#define B_   2
#define S_   2048
#define D_   2048
#define H_   16
#define KV_  4
#define HD_  128
#define NROWS (B_*S_)        // 4096
#define QPK_ (H_/KV_)        // 4

// ---------------- scratch (device globals; no allocation allowed) ----------
__device__ float g_q[(size_t)NROWS * D_];        // [b,s,h,hd]
__device__ float g_k[(size_t)NROWS * KV_ * HD_]; // [b,s,kv,hd]
__device__ float g_v[(size_t)NROWS * KV_ * HD_];
__device__ float g_attn[(size_t)NROWS * D_];     // attention out, [b,s,h,hd]

// ---------------- tf32 helpers ----------------------------------------------
__device__ __forceinline__ unsigned f2tf(float f) {
    unsigned r;
    asm("cvt.rna.tf32.f32 %0, %1;" : "=r"(r) : "f"(f));
    return r;
}

__device__ __forceinline__ void mma_tf32(float c[4],
                                         unsigned a0, unsigned a1,
                                         unsigned a2, unsigned a3,
                                         unsigned b0, unsigned b1) {
    asm volatile(
        "mma.sync.aligned.m16n8k8.row.col.f32.tf32.tf32.f32 "
        "{%0,%1,%2,%3}, {%4,%5,%6,%7}, {%8,%9}, {%0,%1,%2,%3};\n"
        : "+f"(c[0]), "+f"(c[1]), "+f"(c[2]), "+f"(c[3])
        : "r"(a0), "r"(a1), "r"(a2), "r"(a3), "r"(b0), "r"(b1));
}

// ---------------- TF32 tensor-core GEMM: C[M,N] = A[M,K] @ B[K,N] (+bias) ---
__global__ __launch_bounds__(256, 2) void tf32_gemm_kernel(
    const float* __restrict__ A, const float* __restrict__ Bm,
    const float* __restrict__ bias, float* __restrict__ C,
    int M, int N, int K)
{
    __shared__ unsigned As[128][36];
    __shared__ unsigned Bs[32][136];

    const int tid  = threadIdx.x;
    const int warp = tid >> 5;
    const int lane = tid & 31;
    const int wm   = warp >> 2;
    const int wn   = warp & 3;
    const int grp  = lane >> 2;
    const int qid  = lane & 3;
    const int m0   = blockIdx.y * 128;
    const int n0   = blockIdx.x * 128;

    float acc[4][4][4];
#pragma unroll
    for (int mi = 0; mi < 4; mi++)
#pragma unroll
        for (int ni = 0; ni < 4; ni++)
#pragma unroll
            for (int r = 0; r < 4; r++) acc[mi][ni][r] = 0.f;

    const float* Aptr = A + (size_t)m0 * K;
    const float* Bptr = Bm + n0;

    float4 stA[4], stB[4];

#define LOAD_TILES(k0)                                                         \
    {                                                                          \
        _Pragma("unroll")                                                      \
        for (int s = 0; s < 4; s++) {                                          \
            int idx = tid + 256 * s;                                           \
            int r = idx >> 3, c4 = (idx & 7) << 2;                             \
            stA[s] = *(const float4*)(Aptr + (size_t)r * K + (k0) + c4);       \
        }                                                                      \
        _Pragma("unroll")                                                      \
        for (int s = 0; s < 4; s++) {                                          \
            int idx = tid + 256 * s;                                           \
            int r = idx >> 5, c4 = (idx & 31) << 2;                            \
            stB[s] = *(const float4*)(Bptr + (size_t)((k0) + r) * N + c4);     \
        }                                                                      \
    }

#define STORE_TILES()                                                          \
    {                                                                          \
        _Pragma("unroll")                                                      \
        for (int s = 0; s < 4; s++) {                                          \
            int idx = tid + 256 * s;                                           \
            int r = idx >> 3, c4 = (idx & 7) << 2;                             \
            uint4 u;                                                           \
            u.x = f2tf(stA[s].x); u.y = f2tf(stA[s].y);                        \
            u.z = f2tf(stA[s].z); u.w = f2tf(stA[s].w);                        \
            *(uint4*)&As[r][c4] = u;                                           \
        }                                                                      \
        _Pragma("unroll")                                                      \
        for (int s = 0; s < 4; s++) {                                          \
            int idx = tid + 256 * s;                                           \
            int r = idx >> 5, c4 = (idx & 31) << 2;                            \
            uint4 u;                                                           \
            u.x = f2tf(stB[s].x); u.y = f2tf(stB[s].y);                        \
            u.z = f2tf(stB[s].z); u.w = f2tf(stB[s].w);                        \
            *(uint4*)&Bs[r][c4] = u;                                           \
        }                                                                      \
    }

    const int nk = K >> 5;
    LOAD_TILES(0);
    STORE_TILES();
    __syncthreads();

    for (int kt = 0; kt < nk; kt++) {
        if (kt + 1 < nk) LOAD_TILES((kt + 1) << 5);

#pragma unroll
        for (int ks = 0; ks < 4; ks++) {
            const int k = ks * 8;
            unsigned a[4][4], b[4][2];
#pragma unroll
            for (int mi = 0; mi < 4; mi++) {
                int m = wm * 64 + mi * 16;
                a[mi][0] = As[m + grp][k + qid];
                a[mi][1] = As[m + grp + 8][k + qid];
                a[mi][2] = As[m + grp][k + qid + 4];
                a[mi][3] = As[m + grp + 8][k + qid + 4];
            }
#pragma unroll
            for (int ni = 0; ni < 4; ni++) {
                int n = wn * 32 + ni * 8;
                b[ni][0] = Bs[k + qid][n + grp];
                b[ni][1] = Bs[k + qid + 4][n + grp];
            }
#pragma unroll
            for (int mi = 0; mi < 4; mi++)
#pragma unroll
                for (int ni = 0; ni < 4; ni++)
                    mma_tf32(acc[mi][ni],
                             a[mi][0], a[mi][1], a[mi][2], a[mi][3],
                             b[ni][0], b[ni][1]);
        }
        __syncthreads();
        if (kt + 1 < nk) {
            STORE_TILES();
            __syncthreads();
        }
    }

#pragma unroll
    for (int mi = 0; mi < 4; mi++) {
#pragma unroll
        for (int ni = 0; ni < 4; ni++) {
            int row = m0 + wm * 64 + mi * 16 + grp;
            int col = n0 + wn * 32 + ni * 8 + 2 * qid;
            float bx = 0.f, by = 0.f;
            if (bias) { bx = bias[col]; by = bias[col + 1]; }
            float2 v0, v1;
            v0.x = acc[mi][ni][0] + bx; v0.y = acc[mi][ni][1] + by;
            v1.x = acc[mi][ni][2] + bx; v1.y = acc[mi][ni][3] + by;
            *(float2*)(C + (size_t)row * N + col)       = v0;
            *(float2*)(C + (size_t)(row + 8) * N + col) = v1;
        }
    }
#undef LOAD_TILES
#undef STORE_TILES
}

// ---------------- RoPE (interleaved pairs, per reference) -------------------
__global__ void rope_kernel(float* __restrict__ q, float* __restrict__ k,
                            const float* __restrict__ fcos,
                            const float* __restrict__ fsin)
{
    const int NQP = B_ * S_ * H_  * (HD_ / 2);
    const int NKP = B_ * S_ * KV_ * (HD_ / 2);
    int idx = blockIdx.x * blockDim.x + threadIdx.x;
    if (idx < NQP) {
        int j = idx & 63;
        int s = (idx >> 10) & (S_ - 1);
        float c  = fcos[s * 64 + j];
        float sn = fsin[s * 64 + j];
        float2 v = *(float2*)(q + 2 * (size_t)idx);
        float2 o;
        o.x = v.x * c - v.y * sn;
        o.y = v.x * sn + v.y * c;
        *(float2*)(q + 2 * (size_t)idx) = o;
    } else if (idx < NQP + NKP) {
        int p = idx - NQP;
        int j = p & 63;
        int s = (p >> 8) & (S_ - 1);
        float c  = fcos[s * 64 + j];
        float sn = fsin[s * 64 + j];
        float2 v = *(float2*)(k + 2 * (size_t)p);
        float2 o;
        o.x = v.x * c - v.y * sn;
        o.y = v.x * sn + v.y * c;
        *(float2*)(k + 2 * (size_t)p) = o;
    }
}

// ---------------- Tensor-core flash attention (causal, GQA) -----------------
// 128 threads = 4 warps; 64 q-rows per block (16 per warp); kv tiles of 64.
// Q in register fragments (pre-scaled). K smem stride 132 (conflict-free QK
// b-frags), V stride 136 (conflict-free PV b-frags), P stride 68 (conflict-
// free PV a-frags). K and V share one buffer.
#define KS_STRIDE 132
#define VS_STRIDE 136
#define PS_STRIDE 68
#define FA_SMEM ((64*136 + 64*68) * 4)   // 52224 bytes

__global__ __launch_bounds__(128, 2) void flash_attn_tc_kernel(
    const float* __restrict__ Q, const float* __restrict__ Kg,
    const float* __restrict__ Vg, float* __restrict__ O)
{
    extern __shared__ unsigned sm_u[];
    unsigned* KVs = sm_u;                 // K (stride 132) / V (stride 136)
    unsigned* Ps  = sm_u + 64 * 136;      // P tile, stride 68

    const int tid  = threadIdx.x;
    const int w    = tid >> 5;
    const int lane = tid & 31;
    const int g    = lane >> 2;          // 0..7
    const int q    = lane & 3;           // 0..3
    const int qb   = blockIdx.x;         // 0..31
    const int h    = blockIdx.y;
    const int b    = blockIdx.z;
    const int kvh  = h >> 2;
    const float scale = 0.08838834764831845f;   // 1/sqrt(128)

    const int lr0 = w * 16 + g;          // local q-row for c0,c1
    const int lr1 = lr0 + 8;             // local q-row for c2,c3

    // ---- stage Q tile (64 x 128) through smem, pull scaled tf32 fragments --
    const float* qbase = Q + (((size_t)(b * S_ + qb * 64)) * H_ + h) * HD_;
    float* Qstage = (float*)KVs;
#pragma unroll
    for (int s = 0; s < 16; s++) {
        int f = tid + 128 * s;
        int r = f >> 5, c = (f & 31) << 2;
        *(float4*)(Qstage + r * KS_STRIDE + c) =
            *(const float4*)(qbase + (size_t)r * (H_ * HD_) + c);
    }
    __syncthreads();

    unsigned qa[16][4];
#pragma unroll
    for (int ks = 0; ks < 16; ks++) {
        int k = ks * 8;
        qa[ks][0] = f2tf(scale * Qstage[lr0 * KS_STRIDE + k + q]);
        qa[ks][1] = f2tf(scale * Qstage[lr1 * KS_STRIDE + k + q]);
        qa[ks][2] = f2tf(scale * Qstage[lr0 * KS_STRIDE + k + q + 4]);
        qa[ks][3] = f2tf(scale * Qstage[lr1 * KS_STRIDE + k + q + 4]);
    }
    __syncthreads();

    float m0 = -1e30f, m1 = -1e30f, l0 = 0.f, l1 = 0.f;
    float oc[16][4];
#pragma unroll
    for (int nt = 0; nt < 16; nt++)
#pragma unroll
        for (int r = 0; r < 4; r++) oc[nt][r] = 0.f;

    for (int kb = 0; kb <= qb; kb++) {
        // ---- load K tile (64 x 128) as tf32, stride 132 ----
        const float* kbase = Kg + (((size_t)(b * S_ + kb * 64)) * KV_ + kvh) * HD_;
#pragma unroll
        for (int s = 0; s < 16; s++) {
            int f = tid + 128 * s;
            int r = f >> 5, c = (f & 31) << 2;
            float4 v = *(const float4*)(kbase + (size_t)r * (KV_ * HD_) + c);
            uint4 u;
            u.x = f2tf(v.x); u.y = f2tf(v.y); u.z = f2tf(v.z); u.w = f2tf(v.w);
            *(uint4*)(KVs + r * KS_STRIDE + c) = u;
        }
        __syncthreads();

        // ---- S = Q K^T  (8 n-tiles of 8 cols, 16 ksteps) ----
        float sa[8][4];
#pragma unroll
        for (int nt = 0; nt < 8; nt++)
#pragma unroll
            for (int r = 0; r < 4; r++) sa[nt][r] = 0.f;

#pragma unroll
        for (int ks = 0; ks < 16; ks++) {
            int k = ks * 8;
#pragma unroll
            for (int nt = 0; nt < 8; nt++) {
                unsigned b0 = KVs[(nt * 8 + g) * KS_STRIDE + k + q];
                unsigned b1 = KVs[(nt * 8 + g) * KS_STRIDE + k + q + 4];
                mma_tf32(sa[nt], qa[ks][0], qa[ks][1], qa[ks][2], qa[ks][3], b0, b1);
            }
        }
        __syncthreads();   // all warps done reading K

        // ---- load V tile as tf32, stride 136 (no one reads KVs until sync) -
        const float* vbase = Vg + (((size_t)(b * S_ + kb * 64)) * KV_ + kvh) * HD_;
#pragma unroll
        for (int s = 0; s < 16; s++) {
            int f = tid + 128 * s;
            int r = f >> 5, c = (f & 31) << 2;
            float4 v = *(const float4*)(vbase + (size_t)r * (KV_ * HD_) + c);
            uint4 u;
            u.x = f2tf(v.x); u.y = f2tf(v.y); u.z = f2tf(v.z); u.w = f2tf(v.w);
            *(uint4*)(KVs + r * VS_STRIDE + c) = u;
        }

        // ---- causal mask on diagonal tile ----
        if (kb == qb) {
#pragma unroll
            for (int nt = 0; nt < 8; nt++) {
                int c0 = nt * 8 + 2 * q;
                if (c0     > lr0) sa[nt][0] = -1e30f;
                if (c0 + 1 > lr0) sa[nt][1] = -1e30f;
                if (c0     > lr1) sa[nt][2] = -1e30f;
                if (c0 + 1 > lr1) sa[nt][3] = -1e30f;
            }
        }

        // ---- online softmax (rows lr0, lr1; quad-local reduction) ----
        float mx0 = -1e30f, mx1 = -1e30f;
#pragma unroll
        for (int nt = 0; nt < 8; nt++) {
            mx0 = fmaxf(mx0, fmaxf(sa[nt][0], sa[nt][1]));
            mx1 = fmaxf(mx1, fmaxf(sa[nt][2], sa[nt][3]));
        }
#pragma unroll
        for (int off = 1; off <= 2; off <<= 1) {
            mx0 = fmaxf(mx0, __shfl_xor_sync(0xffffffffu, mx0, off));
            mx1 = fmaxf(mx1, __shfl_xor_sync(0xffffffffu, mx1, off));
        }
        float mn0 = fmaxf(m0, mx0), mn1 = fmaxf(m1, mx1);
        float al0 = __expf(m0 - mn0), al1 = __expf(m1 - mn1);
        m0 = mn0; m1 = mn1;

        float rs0 = 0.f, rs1 = 0.f;
#pragma unroll
        for (int nt = 0; nt < 8; nt++) {
            float p0 = __expf(sa[nt][0] - mn0);
            float p1 = __expf(sa[nt][1] - mn0);
            float p2 = __expf(sa[nt][2] - mn1);
            float p3 = __expf(sa[nt][3] - mn1);
            rs0 += p0 + p1;
            rs1 += p2 + p3;
            uint2 u0; u0.x = f2tf(p0); u0.y = f2tf(p1);
            uint2 u1; u1.x = f2tf(p2); u1.y = f2tf(p3);
            *(uint2*)(Ps + lr0 * PS_STRIDE + nt * 8 + 2 * q) = u0;
            *(uint2*)(Ps + lr1 * PS_STRIDE + nt * 8 + 2 * q) = u1;
        }
#pragma unroll
        for (int off = 1; off <= 2; off <<= 1) {
            rs0 += __shfl_xor_sync(0xffffffffu, rs0, off);
            rs1 += __shfl_xor_sync(0xffffffffu, rs1, off);
        }
        l0 = l0 * al0 + rs0;
        l1 = l1 * al1 + rs1;
#pragma unroll
        for (int nt = 0; nt < 16; nt++) {
            oc[nt][0] *= al0; oc[nt][1] *= al0;
            oc[nt][2] *= al1; oc[nt][3] *= al1;
        }
        __syncthreads();   // V staged + P visible within warp

        // ---- O += P V  (16 n-tiles of 8 cols, 8 ksteps over keys) ----
#pragma unroll
        for (int k0 = 0; k0 < 8; k0++) {
            int kk = k0 * 8;
            unsigned a0 = Ps[lr0 * PS_STRIDE + kk + q];
            unsigned a1 = Ps[lr1 * PS_STRIDE + kk + q];
            unsigned a2 = Ps[lr0 * PS_STRIDE + kk + q + 4];
            unsigned a3 = Ps[lr1 * PS_STRIDE + kk + q + 4];
#pragma unroll
            for (int nt = 0; nt < 16; nt++) {
                unsigned b0 = KVs[(kk + q)     * VS_STRIDE + nt * 8 + g];
                unsigned b1 = KVs[(kk + q + 4) * VS_STRIDE + nt * 8 + g];
                mma_tf32(oc[nt], a0, a1, a2, a3, b0, b1);
            }
        }
        __syncthreads();   // done reading V before next K load
    }

    // ---- normalize + write ----
    float inv0 = 1.0f / l0, inv1 = 1.0f / l1;
    float* ob0 = O + (((size_t)(b * S_ + qb * 64 + lr0)) * H_ + h) * HD_;
    float* ob1 = O + (((size_t)(b * S_ + qb * 64 + lr1)) * H_ + h) * HD_;
#pragma unroll
    for (int nt = 0; nt < 16; nt++) {
        float2 v0, v1;
        v0.x = oc[nt][0] * inv0; v0.y = oc[nt][1] * inv0;
        v1.x = oc[nt][2] * inv1; v1.y = oc[nt][3] * inv1;
        *(float2*)(ob0 + nt * 8 + 2 * q) = v0;
        *(float2*)(ob1 + nt * 8 + 2 * q) = v1;
    }
}

// ---------------- launch ----------------------------------------------------
extern "C" void kernel_launch(void* const* d_in, const int* in_sizes, int n_in,
                              void* d_out, int out_size)
{
    const float* x    = (const float*)d_in[0];
    const float* fcos = (const float*)d_in[2];
    const float* fsin = (const float*)d_in[3];
    const float* Wq   = (const float*)d_in[4];
    const float* bq   = (const float*)d_in[5];
    const float* Wk   = (const float*)d_in[6];
    const float* bk   = (const float*)d_in[7];
    const float* Wv   = (const float*)d_in[8];
    const float* bv   = (const float*)d_in[9];
    const float* Wo   = (const float*)d_in[10];
    float* out = (float*)d_out;

    float *q, *k, *v, *attn;
    cudaGetSymbolAddress((void**)&q,    g_q);
    cudaGetSymbolAddress((void**)&k,    g_k);
    cudaGetSymbolAddress((void**)&v,    g_v);
    cudaGetSymbolAddress((void**)&attn, g_attn);

    // QKV projections (+bias) on tensor cores (tf32)
    tf32_gemm_kernel<<<dim3(D_ / 128, NROWS / 128), 256>>>(x, Wq, bq, q, NROWS, D_, D_);
    tf32_gemm_kernel<<<dim3((KV_ * HD_) / 128, NROWS / 128), 256>>>(x, Wk, bk, k, NROWS, KV_ * HD_, D_);
    tf32_gemm_kernel<<<dim3((KV_ * HD_) / 128, NROWS / 128), 256>>>(x, Wv, bv, v, NROWS, KV_ * HD_, D_);

    // RoPE on Q and K (in place)
    {
        const int NQP = B_ * S_ * H_  * (HD_ / 2);
        const int NKP = B_ * S_ * KV_ * (HD_ / 2);
        int total = NQP + NKP;
        rope_kernel<<<(total + 255) / 256, 256>>>(q, k, fcos, fsin);
    }

    // causal flash attention on tensor cores (tf32)
    cudaFuncSetAttribute(flash_attn_tc_kernel,
                         cudaFuncAttributeMaxDynamicSharedMemorySize,
                         FA_SMEM);
    flash_attn_tc_kernel<<<dim3(S_ / 64, H_, B_), 128, FA_SMEM>>>(q, k, v, attn);

    // output projection -> d_out (tf32 tensor cores)
    tf32_gemm_kernel<<<dim3(D_ / 128, NROWS / 128), 256>>>(attn, Wo, nullptr, out, NROWS, D_, D_);
}

// round 6
// speedup vs baseline: 3.6287x; 1.1377x over previous
#include <cuda_runtime.h>
#include <cuda_bf16.h>
#include <math.h>

// Problem constants
#define B_   2
#define S_   2048
#define D_   2048
#define H_   16
#define KV_  4
#define HD_  128
#define NROWS (B_*S_)        // 4096
#define QPK_ (H_/KV_)        // 4

// ---------------- scratch (device globals; no allocation allowed) ----------
__device__ float g_q[(size_t)NROWS * D_];        // [b,s,h,hd]
__device__ float g_k[(size_t)NROWS * KV_ * HD_]; // [b,s,kv,hd]
__device__ float g_v[(size_t)NROWS * KV_ * HD_];
__device__ float g_attn[(size_t)NROWS * D_];     // attention out, [b,s,h,hd]

// ---------------- tf32 / cp.async helpers ------------------------------------
__device__ __forceinline__ unsigned f2tf(float f) {
    unsigned r;
    asm("cvt.rna.tf32.f32 %0, %1;" : "=r"(r) : "f"(f));
    return r;
}

__device__ __forceinline__ void mma_tf32(float c[4],
                                         unsigned a0, unsigned a1,
                                         unsigned a2, unsigned a3,
                                         unsigned b0, unsigned b1) {
    asm volatile(
        "mma.sync.aligned.m16n8k8.row.col.f32.tf32.tf32.f32 "
        "{%0,%1,%2,%3}, {%4,%5,%6,%7}, {%8,%9}, {%0,%1,%2,%3};\n"
        : "+f"(c[0]), "+f"(c[1]), "+f"(c[2]), "+f"(c[3])
        : "r"(a0), "r"(a1), "r"(a2), "r"(a3), "r"(b0), "r"(b1));
}

__device__ __forceinline__ void cp16(float* dst_smem, const float* src_global) {
    unsigned d = (unsigned)__cvta_generic_to_shared(dst_smem);
    asm volatile("cp.async.cg.shared.global [%0], [%1], 16;\n"
                 :: "r"(d), "l"(src_global));
}
#define CP_COMMIT() asm volatile("cp.async.commit_group;\n" ::: "memory")
#define CP_WAIT1()  asm volatile("cp.async.wait_group 1;\n" ::: "memory")

// ---------------- pipelined TF32 GEMM: C = A[M,K] @ B[K,N] (+bias, +RoPE) ----
// 128x128 tile, BK=32, 256 threads = 8 warps, warp tile 64x32.
// Double-buffered fp32 smem tiles filled by cp.async; tf32 cvt at frag load.
// As stride 36 / Bs stride 136 -> conflict-free fragment LDS (proven R3).
// If fcos!=nullptr: fused interleaved RoPE on output pairs (bias first).
#define AS_SZ (128*36)
#define BS_SZ (32*136)
#define GEMM_SMEM ((2*AS_SZ + 2*BS_SZ) * 4)   // 71680 bytes

__global__ __launch_bounds__(256, 2) void tf32_gemm_pipe(
    const float* __restrict__ A, const float* __restrict__ Bm,
    const float* __restrict__ bias, float* __restrict__ C,
    int M, int N, int K,
    const float* __restrict__ fcos, const float* __restrict__ fsin)
{
    extern __shared__ float sh[];
    float* As = sh;              // [2][128][36]
    float* Bs = sh + 2 * AS_SZ;  // [2][32][136]

    const int tid  = threadIdx.x;
    const int warp = tid >> 5;
    const int lane = tid & 31;
    const int wm   = warp >> 2;
    const int wn   = warp & 3;
    const int grp  = lane >> 2;
    const int qid  = lane & 3;
    const int m0   = blockIdx.y * 128;
    const int n0   = blockIdx.x * 128;

    float acc[4][4][4];
#pragma unroll
    for (int mi = 0; mi < 4; mi++)
#pragma unroll
        for (int ni = 0; ni < 4; ni++)
#pragma unroll
            for (int r = 0; r < 4; r++) acc[mi][ni][r] = 0.f;

    const float* Aptr = A + (size_t)m0 * K;
    const float* Bptr = Bm + n0;

    // A tile: 128x32 fp32 = 1024x16B; B tile: 32x128 fp32 = 1024x16B.
#define LOAD_TILE(stg, k0)                                                     \
    {                                                                          \
        float* Ad = As + (stg) * AS_SZ;                                        \
        float* Bd = Bs + (stg) * BS_SZ;                                        \
        _Pragma("unroll")                                                      \
        for (int i = 0; i < 4; i++) {                                          \
            int idx = tid + 256 * i;                                           \
            int r = idx >> 3, c4 = (idx & 7) << 2;                             \
            cp16(Ad + r * 36 + c4, Aptr + (size_t)r * K + (k0) + c4);          \
        }                                                                      \
        _Pragma("unroll")                                                      \
        for (int i = 0; i < 4; i++) {                                          \
            int idx = tid + 256 * i;                                           \
            int r = idx >> 5, c4 = (idx & 31) << 2;                            \
            cp16(Bd + r * 136 + c4, Bptr + (size_t)((k0) + r) * N + c4);       \
        }                                                                      \
    }

    const int nk = K >> 5;           // 64 for K=2048
    LOAD_TILE(0, 0);  CP_COMMIT();
    LOAD_TILE(1, 32); CP_COMMIT();
    CP_WAIT1();                      // tile 0 resident
    __syncthreads();

    for (int kt = 0; kt < nk; kt++) {
        const int stg = kt & 1;
        const float* Ac = As + stg * AS_SZ;
        const float* Bc = Bs + stg * BS_SZ;

#pragma unroll
        for (int ks = 0; ks < 4; ks++) {
            const int k = ks * 8;
            unsigned a[4][4], b[4][2];
#pragma unroll
            for (int mi = 0; mi < 4; mi++) {
                int m = wm * 64 + mi * 16;
                a[mi][0] = f2tf(Ac[(m + grp)     * 36 + k + qid]);
                a[mi][1] = f2tf(Ac[(m + grp + 8) * 36 + k + qid]);
                a[mi][2] = f2tf(Ac[(m + grp)     * 36 + k + qid + 4]);
                a[mi][3] = f2tf(Ac[(m + grp + 8) * 36 + k + qid + 4]);
            }
#pragma unroll
            for (int ni = 0; ni < 4; ni++) {
                int n = wn * 32 + ni * 8;
                b[ni][0] = f2tf(Bc[(k + qid)     * 136 + n + grp]);
                b[ni][1] = f2tf(Bc[(k + qid + 4) * 136 + n + grp]);
            }
#pragma unroll
            for (int mi = 0; mi < 4; mi++)
#pragma unroll
                for (int ni = 0; ni < 4; ni++)
                    mma_tf32(acc[mi][ni],
                             a[mi][0], a[mi][1], a[mi][2], a[mi][3],
                             b[ni][0], b[ni][1]);
        }
        __syncthreads();                 // everyone done with stage `stg`
        if (kt + 2 < nk) LOAD_TILE(stg, (kt + 2) << 5);
        CP_COMMIT();                     // (possibly empty) group, keeps counts
        CP_WAIT1();                      // tile kt+1 resident
        __syncthreads();
    }

    // epilogue: bias add, then optional fused interleaved RoPE
    const bool rope = (fcos != nullptr);
#pragma unroll
    for (int mi = 0; mi < 4; mi++) {
#pragma unroll
        for (int ni = 0; ni < 4; ni++) {
            int row = m0 + wm * 64 + mi * 16 + grp;
            int col = n0 + wn * 32 + ni * 8 + 2 * qid;
            float bx = 0.f, by = 0.f;
            if (bias) { bx = bias[col]; by = bias[col + 1]; }
            float2 v0, v1;
            v0.x = acc[mi][ni][0] + bx; v0.y = acc[mi][ni][1] + by;
            v1.x = acc[mi][ni][2] + bx; v1.y = acc[mi][ni][3] + by;
            if (rope) {
                int j = (col & (HD_ - 1)) >> 1;
                int s0 = row & (S_ - 1);
                int s1 = (row + 8) & (S_ - 1);
                float c0 = fcos[s0 * 64 + j], sn0 = fsin[s0 * 64 + j];
                float c1 = fcos[s1 * 64 + j], sn1 = fsin[s1 * 64 + j];
                float2 r0, r1;
                r0.x = v0.x * c0 - v0.y * sn0;
                r0.y = v0.x * sn0 + v0.y * c0;
                r1.x = v1.x * c1 - v1.y * sn1;
                r1.y = v1.x * sn1 + v1.y * c1;
                v0 = r0; v1 = r1;
            }
            *(float2*)(C + (size_t)row * N + col)       = v0;
            *(float2*)(C + (size_t)(row + 8) * N + col) = v1;
        }
    }
#undef LOAD_TILE
}

// ---------------- Tensor-core flash attention (causal, GQA) -----------------
// (unchanged from round 4 — validated at rel_err 6.1e-4)
#define KS_STRIDE 132
#define VS_STRIDE 136
#define PS_STRIDE 68
#define FA_SMEM ((64*136 + 64*68) * 4)   // 52224 bytes

__global__ __launch_bounds__(128, 2) void flash_attn_tc_kernel(
    const float* __restrict__ Q, const float* __restrict__ Kg,
    const float* __restrict__ Vg, float* __restrict__ O)
{
    extern __shared__ unsigned sm_u[];
    unsigned* KVs = sm_u;
    unsigned* Ps  = sm_u + 64 * 136;

    const int tid  = threadIdx.x;
    const int w    = tid >> 5;
    const int lane = tid & 31;
    const int g    = lane >> 2;
    const int q    = lane & 3;
    const int qb   = blockIdx.x;
    const int h    = blockIdx.y;
    const int b    = blockIdx.z;
    const int kvh  = h >> 2;
    const float scale = 0.08838834764831845f;

    const int lr0 = w * 16 + g;
    const int lr1 = lr0 + 8;

    const float* qbase = Q + (((size_t)(b * S_ + qb * 64)) * H_ + h) * HD_;
    float* Qstage = (float*)KVs;
#pragma unroll
    for (int s = 0; s < 16; s++) {
        int f = tid + 128 * s;
        int r = f >> 5, c = (f & 31) << 2;
        *(float4*)(Qstage + r * KS_STRIDE + c) =
            *(const float4*)(qbase + (size_t)r * (H_ * HD_) + c);
    }
    __syncthreads();

    unsigned qa[16][4];
#pragma unroll
    for (int ks = 0; ks < 16; ks++) {
        int k = ks * 8;
        qa[ks][0] = f2tf(scale * Qstage[lr0 * KS_STRIDE + k + q]);
        qa[ks][1] = f2tf(scale * Qstage[lr1 * KS_STRIDE + k + q]);
        qa[ks][2] = f2tf(scale * Qstage[lr0 * KS_STRIDE + k + q + 4]);
        qa[ks][3] = f2tf(scale * Qstage[lr1 * KS_STRIDE + k + q + 4]);
    }
    __syncthreads();

    float m0 = -1e30f, m1 = -1e30f, l0 = 0.f, l1 = 0.f;
    float oc[16][4];
#pragma unroll
    for (int nt = 0; nt < 16; nt++)
#pragma unroll
        for (int r = 0; r < 4; r++) oc[nt][r] = 0.f;

    for (int kb = 0; kb <= qb; kb++) {
        const float* kbase = Kg + (((size_t)(b * S_ + kb * 64)) * KV_ + kvh) * HD_;
#pragma unroll
        for (int s = 0; s < 16; s++) {
            int f = tid + 128 * s;
            int r = f >> 5, c = (f & 31) << 2;
            float4 v = *(const float4*)(kbase + (size_t)r * (KV_ * HD_) + c);
            uint4 u;
            u.x = f2tf(v.x); u.y = f2tf(v.y); u.z = f2tf(v.z); u.w = f2tf(v.w);
            *(uint4*)(KVs + r * KS_STRIDE + c) = u;
        }
        __syncthreads();

        float sa[8][4];
#pragma unroll
        for (int nt = 0; nt < 8; nt++)
#pragma unroll
            for (int r = 0; r < 4; r++) sa[nt][r] = 0.f;

#pragma unroll
        for (int ks = 0; ks < 16; ks++) {
            int k = ks * 8;
#pragma unroll
            for (int nt = 0; nt < 8; nt++) {
                unsigned b0 = KVs[(nt * 8 + g) * KS_STRIDE + k + q];
                unsigned b1 = KVs[(nt * 8 + g) * KS_STRIDE + k + q + 4];
                mma_tf32(sa[nt], qa[ks][0], qa[ks][1], qa[ks][2], qa[ks][3], b0, b1);
            }
        }
        __syncthreads();

        const float* vbase = Vg + (((size_t)(b * S_ + kb * 64)) * KV_ + kvh) * HD_;
#pragma unroll
        for (int s = 0; s < 16; s++) {
            int f = tid + 128 * s;
            int r = f >> 5, c = (f & 31) << 2;
            float4 v = *(const float4*)(vbase + (size_t)r * (KV_ * HD_) + c);
            uint4 u;
            u.x = f2tf(v.x); u.y = f2tf(v.y); u.z = f2tf(v.z); u.w = f2tf(v.w);
            *(uint4*)(KVs + r * VS_STRIDE + c) = u;
        }

        if (kb == qb) {
#pragma unroll
            for (int nt = 0; nt < 8; nt++) {
                int c0 = nt * 8 + 2 * q;
                if (c0     > lr0) sa[nt][0] = -1e30f;
                if (c0 + 1 > lr0) sa[nt][1] = -1e30f;
                if (c0     > lr1) sa[nt][2] = -1e30f;
                if (c0 + 1 > lr1) sa[nt][3] = -1e30f;
            }
        }

        float mx0 = -1e30f, mx1 = -1e30f;
#pragma unroll
        for (int nt = 0; nt < 8; nt++) {
            mx0 = fmaxf(mx0, fmaxf(sa[nt][0], sa[nt][1]));
            mx1 = fmaxf(mx1, fmaxf(sa[nt][2], sa[nt][3]));
        }
#pragma unroll
        for (int off = 1; off <= 2; off <<= 1) {
            mx0 = fmaxf(mx0, __shfl_xor_sync(0xffffffffu, mx0, off));
            mx1 = fmaxf(mx1, __shfl_xor_sync(0xffffffffu, mx1, off));
        }
        float mn0 = fmaxf(m0, mx0), mn1 = fmaxf(m1, mx1);
        float al0 = __expf(m0 - mn0), al1 = __expf(m1 - mn1);
        m0 = mn0; m1 = mn1;

        float rs0 = 0.f, rs1 = 0.f;
#pragma unroll
        for (int nt = 0; nt < 8; nt++) {
            float p0 = __expf(sa[nt][0] - mn0);
            float p1 = __expf(sa[nt][1] - mn0);
            float p2 = __expf(sa[nt][2] - mn1);
            float p3 = __expf(sa[nt][3] - mn1);
            rs0 += p0 + p1;
            rs1 += p2 + p3;
            uint2 u0; u0.x = f2tf(p0); u0.y = f2tf(p1);
            uint2 u1; u1.x = f2tf(p2); u1.y = f2tf(p3);
            *(uint2*)(Ps + lr0 * PS_STRIDE + nt * 8 + 2 * q) = u0;
            *(uint2*)(Ps + lr1 * PS_STRIDE + nt * 8 + 2 * q) = u1;
        }
#pragma unroll
        for (int off = 1; off <= 2; off <<= 1) {
            rs0 += __shfl_xor_sync(0xffffffffu, rs0, off);
            rs1 += __shfl_xor_sync(0xffffffffu, rs1, off);
        }
        l0 = l0 * al0 + rs0;
        l1 = l1 * al1 + rs1;
#pragma unroll
        for (int nt = 0; nt < 16; nt++) {
            oc[nt][0] *= al0; oc[nt][1] *= al0;
            oc[nt][2] *= al1; oc[nt][3] *= al1;
        }
        __syncthreads();

#pragma unroll
        for (int k0 = 0; k0 < 8; k0++) {
            int kk = k0 * 8;
            unsigned a0 = Ps[lr0 * PS_STRIDE + kk + q];
            unsigned a1 = Ps[lr1 * PS_STRIDE + kk + q];
            unsigned a2 = Ps[lr0 * PS_STRIDE + kk + q + 4];
            unsigned a3 = Ps[lr1 * PS_STRIDE + kk + q + 4];
#pragma unroll
            for (int nt = 0; nt < 16; nt++) {
                unsigned b0 = KVs[(kk + q)     * VS_STRIDE + nt * 8 + g];
                unsigned b1 = KVs[(kk + q + 4) * VS_STRIDE + nt * 8 + g];
                mma_tf32(oc[nt], a0, a1, a2, a3, b0, b1);
            }
        }
        __syncthreads();
    }

    float inv0 = 1.0f / l0, inv1 = 1.0f / l1;
    float* ob0 = O + (((size_t)(b * S_ + qb * 64 + lr0)) * H_ + h) * HD_;
    float* ob1 = O + (((size_t)(b * S_ + qb * 64 + lr1)) * H_ + h) * HD_;
#pragma unroll
    for (int nt = 0; nt < 16; nt++) {
        float2 v0, v1;
        v0.x = oc[nt][0] * inv0; v0.y = oc[nt][1] * inv0;
        v1.x = oc[nt][2] * inv1; v1.y = oc[nt][3] * inv1;
        *(float2*)(ob0 + nt * 8 + 2 * q) = v0;
        *(float2*)(ob1 + nt * 8 + 2 * q) = v1;
    }
}

// ---------------- launch ----------------------------------------------------
extern "C" void kernel_launch(void* const* d_in, const int* in_sizes, int n_in,
                              void* d_out, int out_size)
{
    const float* x    = (const float*)d_in[0];
    const float* fcos = (const float*)d_in[2];
    const float* fsin = (const float*)d_in[3];
    const float* Wq   = (const float*)d_in[4];
    const float* bq   = (const float*)d_in[5];
    const float* Wk   = (const float*)d_in[6];
    const float* bk   = (const float*)d_in[7];
    const float* Wv   = (const float*)d_in[8];
    const float* bv   = (const float*)d_in[9];
    const float* Wo   = (const float*)d_in[10];
    float* out = (float*)d_out;

    float *q, *k, *v, *attn;
    cudaGetSymbolAddress((void**)&q,    g_q);
    cudaGetSymbolAddress((void**)&k,    g_k);
    cudaGetSymbolAddress((void**)&v,    g_v);
    cudaGetSymbolAddress((void**)&attn, g_attn);

    cudaFuncSetAttribute(tf32_gemm_pipe,
                         cudaFuncAttributeMaxDynamicSharedMemorySize, GEMM_SMEM);
    cudaFuncSetAttribute(flash_attn_tc_kernel,
                         cudaFuncAttributeMaxDynamicSharedMemorySize, FA_SMEM);

    // QKV projections (+bias; RoPE fused into Q and K epilogues)
    tf32_gemm_pipe<<<dim3(D_ / 128, NROWS / 128), 256, GEMM_SMEM>>>(
        x, Wq, bq, q, NROWS, D_, D_, fcos, fsin);
    tf32_gemm_pipe<<<dim3((KV_ * HD_) / 128, NROWS / 128), 256, GEMM_SMEM>>>(
        x, Wk, bk, k, NROWS, KV_ * HD_, D_, fcos, fsin);
    tf32_gemm_pipe<<<dim3((KV_ * HD_) / 128, NROWS / 128), 256, GEMM_SMEM>>>(
        x, Wv, bv, v, NROWS, KV_ * HD_, D_, nullptr, nullptr);

    // causal flash attention on tensor cores (tf32)
    flash_attn_tc_kernel<<<dim3(S_ / 64, H_, B_), 128, FA_SMEM>>>(q, k, v, attn);

    // output projection -> d_out
    tf32_gemm_pipe<<<dim3(D_ / 128, NROWS / 128), 256, GEMM_SMEM>>>(
        attn, Wo, nullptr, out, NROWS, D_, D_, nullptr, nullptr);
}

// round 7
// speedup vs baseline: 3.6292x; 1.0001x over previous
#include <cuda_runtime.h>
#include <cuda_bf16.h>
#include <math.h>

// Problem constants
#define B_   2
#define S_   2048
#define D_   2048
#define H_   16
#define KV_  4
#define HD_  128
#define NROWS (B_*S_)        // 4096
#define QPK_ (H_/KV_)        // 4

// ---------------- scratch (device globals; no allocation allowed) ----------
__device__ float g_q[(size_t)NROWS * D_];        // [b,s,h,hd]
__device__ float g_k[(size_t)NROWS * KV_ * HD_]; // [b,s,kv,hd]
__device__ float g_v[(size_t)NROWS * KV_ * HD_];
__device__ float g_attn[(size_t)NROWS * D_];     // attention out, [b,s,h,hd]

// ---------------- tf32 / cp.async helpers ------------------------------------
__device__ __forceinline__ unsigned f2tf(float f) {
    unsigned r;
    asm("cvt.rna.tf32.f32 %0, %1;" : "=r"(r) : "f"(f));
    return r;
}

__device__ __forceinline__ void mma_tf32(float c[4],
                                         unsigned a0, unsigned a1,
                                         unsigned a2, unsigned a3,
                                         unsigned b0, unsigned b1) {
    asm volatile(
        "mma.sync.aligned.m16n8k8.row.col.f32.tf32.tf32.f32 "
        "{%0,%1,%2,%3}, {%4,%5,%6,%7}, {%8,%9}, {%0,%1,%2,%3};\n"
        : "+f"(c[0]), "+f"(c[1]), "+f"(c[2]), "+f"(c[3])
        : "r"(a0), "r"(a1), "r"(a2), "r"(a3), "r"(b0), "r"(b1));
}

__device__ __forceinline__ void cp16(float* dst_smem, const float* src_global) {
    unsigned d = (unsigned)__cvta_generic_to_shared(dst_smem);
    asm volatile("cp.async.cg.shared.global [%0], [%1], 16;\n"
                 :: "r"(d), "l"(src_global));
}
#define CP_COMMIT() asm volatile("cp.async.commit_group;\n" ::: "memory")
#define CP_WAIT1()  asm volatile("cp.async.wait_group 1;\n" ::: "memory")

// ---------------- pipelined TF32 GEMM: C = A[M,K] @ B[K,N] (+bias, +RoPE) ----
// 128x128 tile, BK=32, 256 threads = 8 warps, warp tile 64x32.
// Double-buffered fp32 smem tiles filled by cp.async; tf32 cvt at frag load.
// As stride 36 / Bs stride 136 -> conflict-free fragment LDS (proven R3).
// If fcos!=nullptr: fused interleaved RoPE on output pairs (bias first).
#define AS_SZ (128*36)
#define BS_SZ (32*136)
#define GEMM_SMEM ((2*AS_SZ + 2*BS_SZ) * 4)   // 71680 bytes

__global__ __launch_bounds__(256, 2) void tf32_gemm_pipe(
    const float* __restrict__ A, const float* __restrict__ Bm,
    const float* __restrict__ bias, float* __restrict__ C,
    int M, int N, int K,
    const float* __restrict__ fcos, const float* __restrict__ fsin)
{
    extern __shared__ float sh[];
    float* As = sh;              // [2][128][36]
    float* Bs = sh + 2 * AS_SZ;  // [2][32][136]

    const int tid  = threadIdx.x;
    const int warp = tid >> 5;
    const int lane = tid & 31;
    const int wm   = warp >> 2;
    const int wn   = warp & 3;
    const int grp  = lane >> 2;
    const int qid  = lane & 3;
    const int m0   = blockIdx.y * 128;
    const int n0   = blockIdx.x * 128;

    float acc[4][4][4];
#pragma unroll
    for (int mi = 0; mi < 4; mi++)
#pragma unroll
        for (int ni = 0; ni < 4; ni++)
#pragma unroll
            for (int r = 0; r < 4; r++) acc[mi][ni][r] = 0.f;

    const float* Aptr = A + (size_t)m0 * K;
    const float* Bptr = Bm + n0;

    // A tile: 128x32 fp32 = 1024x16B; B tile: 32x128 fp32 = 1024x16B.
#define LOAD_TILE(stg, k0)                                                     \
    {                                                                          \
        float* Ad = As + (stg) * AS_SZ;                                        \
        float* Bd = Bs + (stg) * BS_SZ;                                        \
        _Pragma("unroll")                                                      \
        for (int i = 0; i < 4; i++) {                                          \
            int idx = tid + 256 * i;                                           \
            int r = idx >> 3, c4 = (idx & 7) << 2;                             \
            cp16(Ad + r * 36 + c4, Aptr + (size_t)r * K + (k0) + c4);          \
        }                                                                      \
        _Pragma("unroll")                                                      \
        for (int i = 0; i < 4; i++) {                                          \
            int idx = tid + 256 * i;                                           \
            int r = idx >> 5, c4 = (idx & 31) << 2;                            \
            cp16(Bd + r * 136 + c4, Bptr + (size_t)((k0) + r) * N + c4);       \
        }                                                                      \
    }

    const int nk = K >> 5;           // 64 for K=2048
    LOAD_TILE(0, 0);  CP_COMMIT();
    LOAD_TILE(1, 32); CP_COMMIT();
    CP_WAIT1();                      // tile 0 resident
    __syncthreads();

    for (int kt = 0; kt < nk; kt++) {
        const int stg = kt & 1;
        const float* Ac = As + stg * AS_SZ;
        const float* Bc = Bs + stg * BS_SZ;

#pragma unroll
        for (int ks = 0; ks < 4; ks++) {
            const int k = ks * 8;
            unsigned a[4][4], b[4][2];
#pragma unroll
            for (int mi = 0; mi < 4; mi++) {
                int m = wm * 64 + mi * 16;
                a[mi][0] = f2tf(Ac[(m + grp)     * 36 + k + qid]);
                a[mi][1] = f2tf(Ac[(m + grp + 8) * 36 + k + qid]);
                a[mi][2] = f2tf(Ac[(m + grp)     * 36 + k + qid + 4]);
                a[mi][3] = f2tf(Ac[(m + grp + 8) * 36 + k + qid + 4]);
            }
#pragma unroll
            for (int ni = 0; ni < 4; ni++) {
                int n = wn * 32 + ni * 8;
                b[ni][0] = f2tf(Bc[(k + qid)     * 136 + n + grp]);
                b[ni][1] = f2tf(Bc[(k + qid + 4) * 136 + n + grp]);
            }
#pragma unroll
            for (int mi = 0; mi < 4; mi++)
#pragma unroll
                for (int ni = 0; ni < 4; ni++)
                    mma_tf32(acc[mi][ni],
                             a[mi][0], a[mi][1], a[mi][2], a[mi][3],
                             b[ni][0], b[ni][1]);
        }
        __syncthreads();                 // everyone done with stage `stg`
        if (kt + 2 < nk) LOAD_TILE(stg, (kt + 2) << 5);
        CP_COMMIT();                     // (possibly empty) group, keeps counts
        CP_WAIT1();                      // tile kt+1 resident
        __syncthreads();
    }

    // epilogue: bias add, then optional fused interleaved RoPE
    const bool rope = (fcos != nullptr);
#pragma unroll
    for (int mi = 0; mi < 4; mi++) {
#pragma unroll
        for (int ni = 0; ni < 4; ni++) {
            int row = m0 + wm * 64 + mi * 16 + grp;
            int col = n0 + wn * 32 + ni * 8 + 2 * qid;
            float bx = 0.f, by = 0.f;
            if (bias) { bx = bias[col]; by = bias[col + 1]; }
            float2 v0, v1;
            v0.x = acc[mi][ni][0] + bx; v0.y = acc[mi][ni][1] + by;
            v1.x = acc[mi][ni][2] + bx; v1.y = acc[mi][ni][3] + by;
            if (rope) {
                int j = (col & (HD_ - 1)) >> 1;
                int s0 = row & (S_ - 1);
                int s1 = (row + 8) & (S_ - 1);
                float c0 = fcos[s0 * 64 + j], sn0 = fsin[s0 * 64 + j];
                float c1 = fcos[s1 * 64 + j], sn1 = fsin[s1 * 64 + j];
                float2 r0, r1;
                r0.x = v0.x * c0 - v0.y * sn0;
                r0.y = v0.x * sn0 + v0.y * c0;
                r1.x = v1.x * c1 - v1.y * sn1;
                r1.y = v1.x * sn1 + v1.y * c1;
                v0 = r0; v1 = r1;
            }
            *(float2*)(C + (size_t)row * N + col)       = v0;
            *(float2*)(C + (size_t)(row + 8) * N + col) = v1;
        }
    }
#undef LOAD_TILE
}

// ---------------- Tensor-core flash attention (causal, GQA) -----------------
// (unchanged from round 4 — validated at rel_err 6.1e-4)
#define KS_STRIDE 132
#define VS_STRIDE 136
#define PS_STRIDE 68
#define FA_SMEM ((64*136 + 64*68) * 4)   // 52224 bytes

__global__ __launch_bounds__(128, 2) void flash_attn_tc_kernel(
    const float* __restrict__ Q, const float* __restrict__ Kg,
    const float* __restrict__ Vg, float* __restrict__ O)
{
    extern __shared__ unsigned sm_u[];
    unsigned* KVs = sm_u;
    unsigned* Ps  = sm_u + 64 * 136;

    const int tid  = threadIdx.x;
    const int w    = tid >> 5;
    const int lane = tid & 31;
    const int g    = lane >> 2;
    const int q    = lane & 3;
    const int qb   = blockIdx.x;
    const int h    = blockIdx.y;
    const int b    = blockIdx.z;
    const int kvh  = h >> 2;
    const float scale = 0.08838834764831845f;

    const int lr0 = w * 16 + g;
    const int lr1 = lr0 + 8;

    const float* qbase = Q + (((size_t)(b * S_ + qb * 64)) * H_ + h) * HD_;
    float* Qstage = (float*)KVs;
#pragma unroll
    for (int s = 0; s < 16; s++) {
        int f = tid + 128 * s;
        int r = f >> 5, c = (f & 31) << 2;
        *(float4*)(Qstage + r * KS_STRIDE + c) =
            *(const float4*)(qbase + (size_t)r * (H_ * HD_) + c);
    }
    __syncthreads();

    unsigned qa[16][4];
#pragma unroll
    for (int ks = 0; ks < 16; ks++) {
        int k = ks * 8;
        qa[ks][0] = f2tf(scale * Qstage[lr0 * KS_STRIDE + k + q]);
        qa[ks][1] = f2tf(scale * Qstage[lr1 * KS_STRIDE + k + q]);
        qa[ks][2] = f2tf(scale * Qstage[lr0 * KS_STRIDE + k + q + 4]);
        qa[ks][3] = f2tf(scale * Qstage[lr1 * KS_STRIDE + k + q + 4]);
    }
    __syncthreads();

    float m0 = -1e30f, m1 = -1e30f, l0 = 0.f, l1 = 0.f;
    float oc[16][4];
#pragma unroll
    for (int nt = 0; nt < 16; nt++)
#pragma unroll
        for (int r = 0; r < 4; r++) oc[nt][r] = 0.f;

    for (int kb = 0; kb <= qb; kb++) {
        const float* kbase = Kg + (((size_t)(b * S_ + kb * 64)) * KV_ + kvh) * HD_;
#pragma unroll
        for (int s = 0; s < 16; s++) {
            int f = tid + 128 * s;
            int r = f >> 5, c = (f & 31) << 2;
            float4 v = *(const float4*)(kbase + (size_t)r * (KV_ * HD_) + c);
            uint4 u;
            u.x = f2tf(v.x); u.y = f2tf(v.y); u.z = f2tf(v.z); u.w = f2tf(v.w);
            *(uint4*)(KVs + r * KS_STRIDE + c) = u;
        }
        __syncthreads();

        float sa[8][4];
#pragma unroll
        for (int nt = 0; nt < 8; nt++)
#pragma unroll
            for (int r = 0; r < 4; r++) sa[nt][r] = 0.f;

#pragma unroll
        for (int ks = 0; ks < 16; ks++) {
            int k = ks * 8;
#pragma unroll
            for (int nt = 0; nt < 8; nt++) {
                unsigned b0 = KVs[(nt * 8 + g) * KS_STRIDE + k + q];
                unsigned b1 = KVs[(nt * 8 + g) * KS_STRIDE + k + q + 4];
                mma_tf32(sa[nt], qa[ks][0], qa[ks][1], qa[ks][2], qa[ks][3], b0, b1);
            }
        }
        __syncthreads();

        const float* vbase = Vg + (((size_t)(b * S_ + kb * 64)) * KV_ + kvh) * HD_;
#pragma unroll
        for (int s = 0; s < 16; s++) {
            int f = tid + 128 * s;
            int r = f >> 5, c = (f & 31) << 2;
            float4 v = *(const float4*)(vbase + (size_t)r * (KV_ * HD_) + c);
            uint4 u;
            u.x = f2tf(v.x); u.y = f2tf(v.y); u.z = f2tf(v.z); u.w = f2tf(v.w);
            *(uint4*)(KVs + r * VS_STRIDE + c) = u;
        }

        if (kb == qb) {
#pragma unroll
            for (int nt = 0; nt < 8; nt++) {
                int c0 = nt * 8 + 2 * q;
                if (c0     > lr0) sa[nt][0] = -1e30f;
                if (c0 + 1 > lr0) sa[nt][1] = -1e30f;
                if (c0     > lr1) sa[nt][2] = -1e30f;
                if (c0 + 1 > lr1) sa[nt][3] = -1e30f;
            }
        }

        float mx0 = -1e30f, mx1 = -1e30f;
#pragma unroll
        for (int nt = 0; nt < 8; nt++) {
            mx0 = fmaxf(mx0, fmaxf(sa[nt][0], sa[nt][1]));
            mx1 = fmaxf(mx1, fmaxf(sa[nt][2], sa[nt][3]));
        }
#pragma unroll
        for (int off = 1; off <= 2; off <<= 1) {
            mx0 = fmaxf(mx0, __shfl_xor_sync(0xffffffffu, mx0, off));
            mx1 = fmaxf(mx1, __shfl_xor_sync(0xffffffffu, mx1, off));
        }
        float mn0 = fmaxf(m0, mx0), mn1 = fmaxf(m1, mx1);
        float al0 = __expf(m0 - mn0), al1 = __expf(m1 - mn1);
        m0 = mn0; m1 = mn1;

        float rs0 = 0.f, rs1 = 0.f;
#pragma unroll
        for (int nt = 0; nt < 8; nt++) {
            float p0 = __expf(sa[nt][0] - mn0);
            float p1 = __expf(sa[nt][1] - mn0);
            float p2 = __expf(sa[nt][2] - mn1);
            float p3 = __expf(sa[nt][3] - mn1);
            rs0 += p0 + p1;
            rs1 += p2 + p3;
            uint2 u0; u0.x = f2tf(p0); u0.y = f2tf(p1);
            uint2 u1; u1.x = f2tf(p2); u1.y = f2tf(p3);
            *(uint2*)(Ps + lr0 * PS_STRIDE + nt * 8 + 2 * q) = u0;
            *(uint2*)(Ps + lr1 * PS_STRIDE + nt * 8 + 2 * q) = u1;
        }
#pragma unroll
        for (int off = 1; off <= 2; off <<= 1) {
            rs0 += __shfl_xor_sync(0xffffffffu, rs0, off);
            rs1 += __shfl_xor_sync(0xffffffffu, rs1, off);
        }
        l0 = l0 * al0 + rs0;
        l1 = l1 * al1 + rs1;
#pragma unroll
        for (int nt = 0; nt < 16; nt++) {
            oc[nt][0] *= al0; oc[nt][1] *= al0;
            oc[nt][2] *= al1; oc[nt][3] *= al1;
        }
        __syncthreads();

#pragma unroll
        for (int k0 = 0; k0 < 8; k0++) {
            int kk = k0 * 8;
            unsigned a0 = Ps[lr0 * PS_STRIDE + kk + q];
            unsigned a1 = Ps[lr1 * PS_STRIDE + kk + q];
            unsigned a2 = Ps[lr0 * PS_STRIDE + kk + q + 4];
            unsigned a3 = Ps[lr1 * PS_STRIDE + kk + q + 4];
#pragma unroll
            for (int nt = 0; nt < 16; nt++) {
                unsigned b0 = KVs[(kk + q)     * VS_STRIDE + nt * 8 + g];
                unsigned b1 = KVs[(kk + q + 4) * VS_STRIDE + nt * 8 + g];
                mma_tf32(oc[nt], a0, a1, a2, a3, b0, b1);
            }
        }
        __syncthreads();
    }

    float inv0 = 1.0f / l0, inv1 = 1.0f / l1;
    float* ob0 = O + (((size_t)(b * S_ + qb * 64 + lr0)) * H_ + h) * HD_;
    float* ob1 = O + (((size_t)(b * S_ + qb * 64 + lr1)) * H_ + h) * HD_;
#pragma unroll
    for (int nt = 0; nt < 16; nt++) {
        float2 v0, v1;
        v0.x = oc[nt][0] * inv0; v0.y = oc[nt][1] * inv0;
        v1.x = oc[nt][2] * inv1; v1.y = oc[nt][3] * inv1;
        *(float2*)(ob0 + nt * 8 + 2 * q) = v0;
        *(float2*)(ob1 + nt * 8 + 2 * q) = v1;
    }
}

// ---------------- launch ----------------------------------------------------
extern "C" void kernel_launch(void* const* d_in, const int* in_sizes, int n_in,
                              void* d_out, int out_size)
{
    const float* x    = (const float*)d_in[0];
    const float* fcos = (const float*)d_in[2];
    const float* fsin = (const float*)d_in[3];
    const float* Wq   = (const float*)d_in[4];
    const float* bq   = (const float*)d_in[5];
    const float* Wk   = (const float*)d_in[6];
    const float* bk   = (const float*)d_in[7];
    const float* Wv   = (const float*)d_in[8];
    const float* bv   = (const float*)d_in[9];
    const float* Wo   = (const float*)d_in[10];
    float* out = (float*)d_out;

    float *q, *k, *v, *attn;
    cudaGetSymbolAddress((void**)&q,    g_q);
    cudaGetSymbolAddress((void**)&k,    g_k);
    cudaGetSymbolAddress((void**)&v,    g_v);
    cudaGetSymbolAddress((void**)&attn, g_attn);

    cudaFuncSetAttribute(tf32_gemm_pipe,
                         cudaFuncAttributeMaxDynamicSharedMemorySize, GEMM_SMEM);
    cudaFuncSetAttribute(flash_attn_tc_kernel,
                         cudaFuncAttributeMaxDynamicSharedMemorySize, FA_SMEM);

    // QKV projections (+bias; RoPE fused into Q and K epilogues)
    tf32_gemm_pipe<<<dim3(D_ / 128, NROWS / 128), 256, GEMM_SMEM>>>(
        x, Wq, bq, q, NROWS, D_, D_, fcos, fsin);
    tf32_gemm_pipe<<<dim3((KV_ * HD_) / 128, NROWS / 128), 256, GEMM_SMEM>>>(
        x, Wk, bk, k, NROWS, KV_ * HD_, D_, fcos, fsin);
    tf32_gemm_pipe<<<dim3((KV_ * HD_) / 128, NROWS / 128), 256, GEMM_SMEM>>>(
        x, Wv, bv, v, NROWS, KV_ * HD_, D_, nullptr, nullptr);

    // causal flash attention on tensor cores (tf32)
    flash_attn_tc_kernel<<<dim3(S_ / 64, H_, B_), 128, FA_SMEM>>>(q, k, v, attn);

    // output projection -> d_out
    tf32_gemm_pipe<<<dim3(D_ / 128, NROWS / 128), 256, GEMM_SMEM>>>(
        attn, Wo, nullptr, out, NROWS, D_, D_, nullptr, nullptr);
}